// round 3
// baseline (speedup 1.0000x reference)
#include <cuda_runtime.h>
#include <cuda_bf16.h>
#include <math.h>

// Problem constants (fixed by the reference)
#define NN 50000          // nodes
#define NE 800000         // edges (without self loops)
#define NT (NE + NN)      // edges + self loops
#define FIN 128
#define F1 256            // HEADS*OUT_CH
#define H1HEADS 4
#define F2 64
#define NEG_SLOPE 0.2f

// -------- scratch (device globals; referenced by symbol inside kernels) --------
__device__ float g_h1[NN * F1];      // layer1 features per node
__device__ float g_out1[NN * F1];    // relu(gat1 output)
__device__ float g_h2[NN * F2];      // layer2 features per node
__device__ float g_as1[NN * H1HEADS];
__device__ float g_ad1[NN * H1HEADS];
__device__ float g_as2[NN];
__device__ float g_ad2[NN];
__device__ int   g_deg[NN];
__device__ int   g_rowptr[NN + 1];
__device__ int   g_fill[NN];
__device__ int   g_csrsrc[NT];

// ---------------- CSR build ----------------
__global__ void k_deg_init() {
    int i = blockIdx.x * blockDim.x + threadIdx.x;
    if (i < NN) g_deg[i] = 1;   // self loop
}

__global__ void k_count(const int* __restrict__ edge) {
    int e = blockIdx.x * blockDim.x + threadIdx.x;
    if (e < NE) {
        int d = edge[NE + e];   // dst row (int32 — JAX x64 disabled)
        atomicAdd(&g_deg[d], 1);
    }
}

__global__ void k_scan() {
    __shared__ int sh[1024];
    __shared__ int soff;
    if (threadIdx.x == 0) soff = 0;
    __syncthreads();
    for (int base = 0; base < NN; base += 1024) {
        int i = base + threadIdx.x;
        int v = (i < NN) ? g_deg[i] : 0;
        sh[threadIdx.x] = v;
        __syncthreads();
        #pragma unroll
        for (int off = 1; off < 1024; off <<= 1) {
            int t = (threadIdx.x >= off) ? sh[threadIdx.x - off] : 0;
            __syncthreads();
            sh[threadIdx.x] += t;
            __syncthreads();
        }
        int incl = sh[threadIdx.x];
        if (i < NN) g_rowptr[i] = soff + incl - v;  // exclusive
        __syncthreads();
        if (threadIdx.x == 1023) soff += sh[1023];
        __syncthreads();
    }
    if (threadIdx.x == 0) g_rowptr[NN] = soff;
}

__global__ void k_fillcopy() {
    int i = blockIdx.x * blockDim.x + threadIdx.x;
    if (i < NN) g_fill[i] = g_rowptr[i];
}

__global__ void k_scatter(const int* __restrict__ edge) {
    int t = blockIdx.x * blockDim.x + threadIdx.x;
    if (t < NE) {
        int d = edge[NE + t];
        int s = edge[t];
        int pos = atomicAdd(&g_fill[d], 1);
        g_csrsrc[pos] = s;
    } else if (t < NT) {
        int i = t - NE;
        int pos = atomicAdd(&g_fill[i], 1);
        g_csrsrc[pos] = i;
    }
}

// ---------------- tiled SGEMM body: C[M,N] = A[M,K] @ B[K,N] ----------------
template <int BM, int BN, int BK, int TM, int TN>
__device__ __forceinline__
void sgemm_body(const float* __restrict__ A, const float* __restrict__ B,
                float* __restrict__ C, int M, int K, int N) {
    __shared__ float As[BM][BK + 1];
    __shared__ float Bs[BK][BN];
    const int tx = threadIdx.x;
    const int tcol = tx % (BN / TN);
    const int trow = tx / (BN / TN);
    const int rowBase = blockIdx.x * BM;
    const int colBase = blockIdx.y * BN;

    float acc[TM][TN];
    #pragma unroll
    for (int i = 0; i < TM; i++)
        #pragma unroll
        for (int j = 0; j < TN; j++) acc[i][j] = 0.f;

    for (int k0 = 0; k0 < K; k0 += BK) {
        #pragma unroll
        for (int i = tx; i < BM * BK; i += 256) {
            int r = i / BK, c = i % BK;
            int gr = rowBase + r;
            As[r][c] = (gr < M) ? A[(long long)gr * K + k0 + c] : 0.f;
        }
        #pragma unroll
        for (int i = tx; i < BK * BN; i += 256) {
            int r = i / BN, c = i % BN;
            Bs[r][c] = B[(k0 + r) * N + colBase + c];
        }
        __syncthreads();
        #pragma unroll
        for (int k = 0; k < BK; k++) {
            float a[TM], b[TN];
            #pragma unroll
            for (int i = 0; i < TM; i++) a[i] = As[trow * TM + i][k];
            #pragma unroll
            for (int j = 0; j < TN; j += 4) {
                float4 bv = *(const float4*)&Bs[k][tcol * TN + j];
                b[j] = bv.x; b[j + 1] = bv.y; b[j + 2] = bv.z; b[j + 3] = bv.w;
            }
            #pragma unroll
            for (int i = 0; i < TM; i++)
                #pragma unroll
                for (int j = 0; j < TN; j++)
                    acc[i][j] = fmaf(a[i], b[j], acc[i][j]);
        }
        __syncthreads();
    }
    #pragma unroll
    for (int i = 0; i < TM; i++) {
        int gr = rowBase + trow * TM + i;
        if (gr >= M) continue;
        #pragma unroll
        for (int j = 0; j < TN; j++)
            C[(long long)gr * N + colBase + tcol * TN + j] = acc[i][j];
    }
}

// GEMM1: A = x (input param), C = g_h1
__global__ __launch_bounds__(256)
void sgemm1_kernel(const float* __restrict__ A, const float* __restrict__ B) {
    sgemm_body<128, 128, 16, 8, 8>(A, B, g_h1, NN, FIN, F1);
}

// GEMM2: A = g_out1 (global), C = g_h2
__global__ __launch_bounds__(256)
void sgemm2_kernel(const float* __restrict__ B) {
    sgemm_body<128, 64, 16, 8, 4>(g_out1, B, g_h2, NN, F1, F2);
}

// ---------------- alpha projections ----------------
__global__ void alpha1_kernel(const float* __restrict__ a_src,
                              const float* __restrict__ a_dst) {
    int warp = threadIdx.x >> 5, lane = threadIdx.x & 31;
    int node = blockIdx.x * 2 + (warp >> 2);
    int h = warp & 3;
    if (node >= NN) return;
    const float* row = g_h1 + (long long)node * F1 + h * 64;
    float v0 = row[lane], v1 = row[lane + 32];
    float s = v0 * a_src[h * 64 + lane] + v1 * a_src[h * 64 + lane + 32];
    float d = v0 * a_dst[h * 64 + lane] + v1 * a_dst[h * 64 + lane + 32];
    #pragma unroll
    for (int o = 16; o > 0; o >>= 1) {
        s += __shfl_down_sync(0xffffffffu, s, o);
        d += __shfl_down_sync(0xffffffffu, d, o);
    }
    if (lane == 0) { g_as1[node * 4 + h] = s; g_ad1[node * 4 + h] = d; }
}

__global__ void alpha2_kernel(const float* __restrict__ a_src,
                              const float* __restrict__ a_dst) {
    int warp = threadIdx.x >> 5, lane = threadIdx.x & 31;
    int node = blockIdx.x * 8 + warp;
    if (node >= NN) return;
    float v0 = g_h2[(long long)node * F2 + lane];
    float v1 = g_h2[(long long)node * F2 + lane + 32];
    float s = v0 * a_src[lane] + v1 * a_src[lane + 32];
    float d = v0 * a_dst[lane] + v1 * a_dst[lane + 32];
    #pragma unroll
    for (int o = 16; o > 0; o >>= 1) {
        s += __shfl_down_sync(0xffffffffu, s, o);
        d += __shfl_down_sync(0xffffffffu, d, o);
    }
    if (lane == 0) { g_as2[node] = s; g_ad2[node] = d; }
}

__device__ __forceinline__ float lrelu(float x) {
    return x > 0.f ? x : NEG_SLOPE * x;
}

// ---------------- layer 1 aggregation: 1 block (256 thr) per dst ----------------
__global__ __launch_bounds__(256)
void agg1_kernel(const float* __restrict__ b1) {
    int d = blockIdx.x;
    int c = threadIdx.x;           // channel 0..255
    int h = c >> 6;                // head
    int beg = g_rowptr[d], end = g_rowptr[d + 1];
    float adv = g_ad1[d * 4 + h];

    // pass A: per-head max over incident edges
    float m = -1e30f;
    for (int i = beg + (c & 63); i < end; i += 64) {
        int s = g_csrsrc[i];
        m = fmaxf(m, lrelu(g_as1[s * 4 + h] + adv));
    }
    #pragma unroll
    for (int o = 16; o > 0; o >>= 1) m = fmaxf(m, __shfl_xor_sync(0xffffffffu, m, o));
    __shared__ float smax[8];
    int warp = c >> 5;
    if ((c & 31) == 0) smax[warp] = m;
    __syncthreads();
    float mh = fmaxf(smax[2 * h], smax[2 * h + 1]);

    // pass B: weighted sum + denom in one sweep
    float acc = 0.f, den = 0.f;
    for (int i = beg; i < end; i++) {
        int s = g_csrsrc[i];
        float e = lrelu(g_as1[s * 4 + h] + adv);
        float p = __expf(e - mh);
        den += p;
        acc = fmaf(p, g_h1[(long long)s * F1 + c], acc);
    }
    float o = acc / (den + 1e-16f) + b1[c];
    g_out1[(long long)d * F1 + c] = o > 0.f ? o : 0.f;   // relu between layers
}

// ---------------- layer 2 aggregation: 1 block (64 thr) per dst ----------------
__global__ __launch_bounds__(64)
void agg2_kernel(const float* __restrict__ b2, float* __restrict__ out) {
    int d = blockIdx.x;
    int c = threadIdx.x;           // 0..63
    int beg = g_rowptr[d], end = g_rowptr[d + 1];
    float adv = g_ad2[d];

    float m = -1e30f;
    for (int i = beg + c; i < end; i += 64) {
        int s = g_csrsrc[i];
        m = fmaxf(m, lrelu(g_as2[s] + adv));
    }
    #pragma unroll
    for (int o = 16; o > 0; o >>= 1) m = fmaxf(m, __shfl_xor_sync(0xffffffffu, m, o));
    __shared__ float sm2[2];
    if ((c & 31) == 0) sm2[c >> 5] = m;
    __syncthreads();
    float mh = fmaxf(sm2[0], sm2[1]);

    float acc = 0.f, den = 0.f;
    for (int i = beg; i < end; i++) {
        int s = g_csrsrc[i];
        float e = lrelu(g_as2[s] + adv);
        float p = __expf(e - mh);
        den += p;
        acc = fmaf(p, g_h2[(long long)s * F2 + c], acc);
    }
    out[(long long)d * F2 + c] = acc / (den + 1e-16f) + b2[c];
}

// ---------------- launch ----------------
extern "C" void kernel_launch(void* const* d_in, const int* in_sizes, int n_in,
                              void* d_out, int out_size) {
    const float* x      = (const float*)d_in[0];
    const int*   edge   = (const int*)d_in[1];   // int32! (JAX x64 disabled)
    const float* W1     = (const float*)d_in[2];
    const float* a_src1 = (const float*)d_in[3];
    const float* a_dst1 = (const float*)d_in[4];
    const float* b1     = (const float*)d_in[5];
    const float* W2     = (const float*)d_in[6];
    const float* a_src2 = (const float*)d_in[7];
    const float* a_dst2 = (const float*)d_in[8];
    const float* b2     = (const float*)d_in[9];
    float* out = (float*)d_out;

    // CSR by dst (rebuilt every call — same inputs, same work)
    k_deg_init<<<(NN + 255) / 256, 256>>>();
    k_count<<<(NE + 255) / 256, 256>>>(edge);
    k_scan<<<1, 1024>>>();
    k_fillcopy<<<(NN + 255) / 256, 256>>>();
    k_scatter<<<(NT + 255) / 256, 256>>>(edge);

    // layer 1
    {
        dim3 grid((NN + 127) / 128, F1 / 128);
        sgemm1_kernel<<<grid, 256>>>(x, W1);
    }
    alpha1_kernel<<<(NN + 1) / 2, 256>>>(a_src1, a_dst1);
    agg1_kernel<<<NN, 256>>>(b1);

    // layer 2 (g_out1 already relu'd)
    {
        dim3 grid((NN + 127) / 128, 1);
        sgemm2_kernel<<<grid, 256>>>(W2);
    }
    alpha2_kernel<<<(NN + 7) / 8, 256>>>(a_src2, a_dst2);
    agg2_kernel<<<NN, 64>>>(b2, out);
}

// round 4
// speedup vs baseline: 1.4735x; 1.4735x over previous
#include <cuda_runtime.h>
#include <cuda_bf16.h>
#include <math.h>

// Problem constants (fixed by the reference)
#define NN 50000          // nodes
#define NE 800000         // edges (without self loops)
#define NT (NE + NN)      // edges + self loops
#define FIN 128
#define F1 256            // HEADS*OUT_CH
#define H1HEADS 4
#define F2 64
#define NEG_SLOPE 0.2f

// -------- scratch (device globals) --------
__device__ float g_h1[NN * F1];      // layer1 features per node
__device__ float g_out1[NN * F1];    // relu(gat1 output)
__device__ float g_h2[NN * F2];      // layer2 features per node
__device__ float g_as1[NN * H1HEADS];
__device__ float g_ad1[NN * H1HEADS];
__device__ float g_as2[NN];
__device__ float g_ad2[NN];
__device__ int   g_deg[NN];
__device__ int   g_rowptr[NN + 1];
__device__ int   g_fill[NN];
__device__ int   g_csrsrc[NT];

// ---------------- CSR build ----------------
__global__ void k_deg_init() {
    int i = blockIdx.x * blockDim.x + threadIdx.x;
    if (i < NN) g_deg[i] = 1;   // self loop
}

__global__ void k_count(const int* __restrict__ edge) {
    int e = blockIdx.x * blockDim.x + threadIdx.x;
    if (e < NE) atomicAdd(&g_deg[edge[NE + e]], 1);
}

// shfl-based block scan, 4 elems/thread, writes rowptr + fill
__global__ __launch_bounds__(1024) void k_scan() {
    __shared__ int sw[33];
    __shared__ int s_base;
    if (threadIdx.x == 0) s_base = 0;
    __syncthreads();
    const int lane = threadIdx.x & 31, warp = threadIdx.x >> 5;
    for (int base = 0; base < NN; base += 4096) {
        int idx = base + threadIdx.x * 4;
        int v0 = 0, v1 = 0, v2 = 0, v3 = 0;
        if (idx + 3 < NN) {
            int4 v = *(const int4*)&g_deg[idx];
            v0 = v.x; v1 = v.y; v2 = v.z; v3 = v.w;
        } else {
            if (idx     < NN) v0 = g_deg[idx];
            if (idx + 1 < NN) v1 = g_deg[idx + 1];
            if (idx + 2 < NN) v2 = g_deg[idx + 2];
            if (idx + 3 < NN) v3 = g_deg[idx + 3];
        }
        int s0 = v0, s1 = s0 + v1, s2 = s1 + v2, s3 = s2 + v3;   // local inclusive
        int incl = s3;
        #pragma unroll
        for (int o = 1; o < 32; o <<= 1) {
            int t = __shfl_up_sync(0xffffffffu, incl, o);
            if (lane >= o) incl += t;
        }
        if (lane == 31) sw[warp + 1] = incl;   // warp total
        __syncthreads();
        if (threadIdx.x == 0) {
            sw[0] = 0;
            int acc = 0;
            #pragma unroll
            for (int w = 1; w <= 32; w++) { acc += sw[w]; sw[w] = acc; }
        }
        __syncthreads();
        int tbase = s_base + sw[warp] + (incl - s3);   // exclusive prefix for this thread
        if (idx     < NN) { g_rowptr[idx]     = tbase;      g_fill[idx]     = tbase; }
        if (idx + 1 < NN) { g_rowptr[idx + 1] = tbase + s0; g_fill[idx + 1] = tbase + s0; }
        if (idx + 2 < NN) { g_rowptr[idx + 2] = tbase + s1; g_fill[idx + 2] = tbase + s1; }
        if (idx + 3 < NN) { g_rowptr[idx + 3] = tbase + s2; g_fill[idx + 3] = tbase + s2; }
        __syncthreads();
        if (threadIdx.x == 0) s_base += sw[32];
        __syncthreads();
    }
    if (threadIdx.x == 0) g_rowptr[NN] = s_base;
}

__global__ void k_scatter(const int* __restrict__ edge) {
    int t = blockIdx.x * blockDim.x + threadIdx.x;
    if (t < NE) {
        int d = edge[NE + t];
        int s = edge[t];
        int pos = atomicAdd(&g_fill[d], 1);
        g_csrsrc[pos] = s;
    } else if (t < NT) {
        int i = t - NE;
        int pos = atomicAdd(&g_fill[i], 1);
        g_csrsrc[pos] = i;
    }
}

// ---------------- tiled SGEMM body: C[M,N] = A[M,K] @ B[K,N] ----------------
template <int BM, int BN, int BK, int TM, int TN>
__device__ __forceinline__
void sgemm_body(const float* __restrict__ A, const float* __restrict__ B,
                float* __restrict__ C, int M, int K, int N) {
    __shared__ float As[BM][BK + 1];
    __shared__ float Bs[BK][BN];
    const int tx = threadIdx.x;
    const int tcol = tx % (BN / TN);
    const int trow = tx / (BN / TN);
    const int rowBase = blockIdx.x * BM;
    const int colBase = blockIdx.y * BN;

    float acc[TM][TN];
    #pragma unroll
    for (int i = 0; i < TM; i++)
        #pragma unroll
        for (int j = 0; j < TN; j++) acc[i][j] = 0.f;

    for (int k0 = 0; k0 < K; k0 += BK) {
        #pragma unroll
        for (int i = tx; i < BM * BK; i += 256) {
            int r = i / BK, c = i % BK;
            int gr = rowBase + r;
            As[r][c] = (gr < M) ? A[(long long)gr * K + k0 + c] : 0.f;
        }
        #pragma unroll
        for (int i = tx; i < BK * BN; i += 256) {
            int r = i / BN, c = i % BN;
            Bs[r][c] = B[(k0 + r) * N + colBase + c];
        }
        __syncthreads();
        #pragma unroll
        for (int k = 0; k < BK; k++) {
            float a[TM], b[TN];
            #pragma unroll
            for (int i = 0; i < TM; i++) a[i] = As[trow * TM + i][k];
            #pragma unroll
            for (int j = 0; j < TN; j += 4) {
                float4 bv = *(const float4*)&Bs[k][tcol * TN + j];
                b[j] = bv.x; b[j + 1] = bv.y; b[j + 2] = bv.z; b[j + 3] = bv.w;
            }
            #pragma unroll
            for (int i = 0; i < TM; i++)
                #pragma unroll
                for (int j = 0; j < TN; j++)
                    acc[i][j] = fmaf(a[i], b[j], acc[i][j]);
        }
        __syncthreads();
    }
    #pragma unroll
    for (int i = 0; i < TM; i++) {
        int gr = rowBase + trow * TM + i;
        if (gr >= M) continue;
        #pragma unroll
        for (int j = 0; j < TN; j++)
            C[(long long)gr * N + colBase + tcol * TN + j] = acc[i][j];
    }
}

__global__ __launch_bounds__(256)
void sgemm1_kernel(const float* __restrict__ A, const float* __restrict__ B) {
    sgemm_body<128, 128, 16, 8, 8>(A, B, g_h1, NN, FIN, F1);
}

__global__ __launch_bounds__(256)
void sgemm2_kernel(const float* __restrict__ B) {
    sgemm_body<128, 64, 16, 8, 4>(g_out1, B, g_h2, NN, F1, F2);
}

// ---------------- alpha projections ----------------
__global__ void alpha1_kernel(const float* __restrict__ a_src,
                              const float* __restrict__ a_dst) {
    int warp = threadIdx.x >> 5, lane = threadIdx.x & 31;
    int node = blockIdx.x * 2 + (warp >> 2);
    int h = warp & 3;
    if (node >= NN) return;
    const float* row = g_h1 + (long long)node * F1 + h * 64;
    float v0 = row[lane], v1 = row[lane + 32];
    float s = v0 * a_src[h * 64 + lane] + v1 * a_src[h * 64 + lane + 32];
    float d = v0 * a_dst[h * 64 + lane] + v1 * a_dst[h * 64 + lane + 32];
    #pragma unroll
    for (int o = 16; o > 0; o >>= 1) {
        s += __shfl_down_sync(0xffffffffu, s, o);
        d += __shfl_down_sync(0xffffffffu, d, o);
    }
    if (lane == 0) { g_as1[node * 4 + h] = s; g_ad1[node * 4 + h] = d; }
}

__global__ void alpha2_kernel(const float* __restrict__ a_src,
                              const float* __restrict__ a_dst) {
    int warp = threadIdx.x >> 5, lane = threadIdx.x & 31;
    int node = blockIdx.x * 8 + warp;
    if (node >= NN) return;
    float v0 = g_h2[(long long)node * F2 + lane];
    float v1 = g_h2[(long long)node * F2 + lane + 32];
    float s = v0 * a_src[lane] + v1 * a_src[lane + 32];
    float d = v0 * a_dst[lane] + v1 * a_dst[lane + 32];
    #pragma unroll
    for (int o = 16; o > 0; o >>= 1) {
        s += __shfl_down_sync(0xffffffffu, s, o);
        d += __shfl_down_sync(0xffffffffu, d, o);
    }
    if (lane == 0) { g_as2[node] = s; g_ad2[node] = d; }
}

__device__ __forceinline__ float lrelu(float x) {
    return x > 0.f ? x : NEG_SLOPE * x;
}

// ---------------- layer 1 aggregation: 64 threads per dst, float4 channels ----
__global__ __launch_bounds__(64)
void agg1_kernel(const float* __restrict__ b1) {
    int d = blockIdx.x;
    int t = threadIdx.x;           // 0..63; channels 4t..4t+3
    int h = t >> 4;                // head (16 threads per head)
    int beg = g_rowptr[d], end = g_rowptr[d + 1];
    float adv = g_ad1[d * 4 + h];

    // pass A: per-head max (16 threads stride the edge list per head)
    float m = -1e30f;
    for (int i = beg + (t & 15); i < end; i += 16) {
        int s = g_csrsrc[i];
        m = fmaxf(m, lrelu(g_as1[s * 4 + h] + adv));
    }
    #pragma unroll
    for (int o = 8; o > 0; o >>= 1)
        m = fmaxf(m, __shfl_xor_sync(0xffffffffu, m, o, 16));

    // pass B: weighted float4 accumulation, unrolled by 2
    const float4* __restrict__ h1v = (const float4*)g_h1;
    float ax = 0.f, ay = 0.f, az = 0.f, aw = 0.f, den = 0.f;
    int i = beg;
    for (; i + 1 < end; i += 2) {
        int s0 = g_csrsrc[i], s1 = g_csrsrc[i + 1];
        float4 v0 = h1v[(long long)s0 * 64 + t];
        float4 v1 = h1v[(long long)s1 * 64 + t];
        float p0 = __expf(lrelu(g_as1[s0 * 4 + h] + adv) - m);
        float p1 = __expf(lrelu(g_as1[s1 * 4 + h] + adv) - m);
        den += p0 + p1;
        ax = fmaf(p0, v0.x, ax); ax = fmaf(p1, v1.x, ax);
        ay = fmaf(p0, v0.y, ay); ay = fmaf(p1, v1.y, ay);
        az = fmaf(p0, v0.z, az); az = fmaf(p1, v1.z, az);
        aw = fmaf(p0, v0.w, aw); aw = fmaf(p1, v1.w, aw);
    }
    if (i < end) {
        int s0 = g_csrsrc[i];
        float4 v0 = h1v[(long long)s0 * 64 + t];
        float p0 = __expf(lrelu(g_as1[s0 * 4 + h] + adv) - m);
        den += p0;
        ax = fmaf(p0, v0.x, ax); ay = fmaf(p0, v0.y, ay);
        az = fmaf(p0, v0.z, az); aw = fmaf(p0, v0.w, aw);
    }
    float inv = 1.f / (den + 1e-16f);
    float4 bv = ((const float4*)b1)[t];
    float4 o;
    o.x = fmaxf(ax * inv + bv.x, 0.f);
    o.y = fmaxf(ay * inv + bv.y, 0.f);
    o.z = fmaxf(az * inv + bv.z, 0.f);
    o.w = fmaxf(aw * inv + bv.w, 0.f);
    ((float4*)g_out1)[(long long)d * 64 + t] = o;
}

// ---------------- layer 2 aggregation: 4 dsts per 64-thread block ------------
__global__ __launch_bounds__(64)
void agg2_kernel(const float* __restrict__ b2, float* __restrict__ out) {
    int t = threadIdx.x;
    int g = t >> 4;                // sub-group 0..3 -> dst
    int l = t & 15;                // lane in group; channels 4l..4l+3
    int d = blockIdx.x * 4 + g;
    if (d >= NN) return;
    int beg = g_rowptr[d], end = g_rowptr[d + 1];
    float adv = g_ad2[d];

    float m = -1e30f;
    for (int i = beg + l; i < end; i += 16) {
        int s = g_csrsrc[i];
        m = fmaxf(m, lrelu(g_as2[s] + adv));
    }
    #pragma unroll
    for (int o = 8; o > 0; o >>= 1)
        m = fmaxf(m, __shfl_xor_sync(0xffffffffu, m, o, 16));

    const float4* __restrict__ h2v = (const float4*)g_h2;
    float ax = 0.f, ay = 0.f, az = 0.f, aw = 0.f, den = 0.f;
    int i = beg;
    for (; i + 1 < end; i += 2) {
        int s0 = g_csrsrc[i], s1 = g_csrsrc[i + 1];
        float4 v0 = h2v[(long long)s0 * 16 + l];
        float4 v1 = h2v[(long long)s1 * 16 + l];
        float p0 = __expf(lrelu(g_as2[s0] + adv) - m);
        float p1 = __expf(lrelu(g_as2[s1] + adv) - m);
        den += p0 + p1;
        ax = fmaf(p0, v0.x, ax); ax = fmaf(p1, v1.x, ax);
        ay = fmaf(p0, v0.y, ay); ay = fmaf(p1, v1.y, ay);
        az = fmaf(p0, v0.z, az); az = fmaf(p1, v1.z, az);
        aw = fmaf(p0, v0.w, aw); aw = fmaf(p1, v1.w, aw);
    }
    if (i < end) {
        int s0 = g_csrsrc[i];
        float4 v0 = h2v[(long long)s0 * 16 + l];
        float p0 = __expf(lrelu(g_as2[s0] + adv) - m);
        den += p0;
        ax = fmaf(p0, v0.x, ax); ay = fmaf(p0, v0.y, ay);
        az = fmaf(p0, v0.z, az); aw = fmaf(p0, v0.w, aw);
    }
    float inv = 1.f / (den + 1e-16f);
    float4 bv = ((const float4*)b2)[l];
    float4 o;
    o.x = ax * inv + bv.x;
    o.y = ay * inv + bv.y;
    o.z = az * inv + bv.z;
    o.w = aw * inv + bv.w;
    ((float4*)out)[(long long)d * 16 + l] = o;
}

// ---------------- launch ----------------
extern "C" void kernel_launch(void* const* d_in, const int* in_sizes, int n_in,
                              void* d_out, int out_size) {
    const float* x      = (const float*)d_in[0];
    const int*   edge   = (const int*)d_in[1];   // int32 (JAX x64 disabled)
    const float* W1     = (const float*)d_in[2];
    const float* a_src1 = (const float*)d_in[3];
    const float* a_dst1 = (const float*)d_in[4];
    const float* b1     = (const float*)d_in[5];
    const float* W2     = (const float*)d_in[6];
    const float* a_src2 = (const float*)d_in[7];
    const float* a_dst2 = (const float*)d_in[8];
    const float* b2     = (const float*)d_in[9];
    float* out = (float*)d_out;

    // launch idx 0..2: CSR prefix (cheap) — puts sgemm1 at the profiled slot
    k_deg_init<<<(NN + 255) / 256, 256>>>();
    k_count<<<(NE + 255) / 256, 256>>>(edge);
    k_scan<<<1, 1024>>>();

    // idx 3: GEMM1 (profiled next round)
    {
        dim3 grid((NN + 127) / 128, F1 / 128);
        sgemm1_kernel<<<grid, 256>>>(x, W1);
    }

    k_scatter<<<(NT + 255) / 256, 256>>>(edge);
    alpha1_kernel<<<(NN + 1) / 2, 256>>>(a_src1, a_dst1);
    agg1_kernel<<<NN, 64>>>(b1);

    {
        dim3 grid((NN + 127) / 128, 1);
        sgemm2_kernel<<<grid, 256>>>(W2);
    }
    alpha2_kernel<<<(NN + 7) / 8, 256>>>(a_src2, a_dst2);
    agg2_kernel<<<(NN + 3) / 4, 64>>>(b2, out);
}

// round 5
// speedup vs baseline: 1.8775x; 1.2742x over previous
#include <cuda_runtime.h>
#include <cuda_bf16.h>
#include <math.h>

#define NN 50000
#define NE 800000
#define NT (NE + NN)
#define FIN 128
#define F1 256
#define H1HEADS 4
#define F2 64
#define NEG_SLOPE 0.2f

// -------- scratch (device globals) --------
__device__ float g_h1[NN * F1];
__device__ float g_out1[NN * F1];
__device__ float g_h2[NN * F2];
__device__ float g_as1[NN * H1HEADS];
__device__ float g_ad1[NN * H1HEADS];
__device__ float g_as2[NN];
__device__ float g_ad2[NN];
__device__ int   g_deg[NN];
__device__ int   g_rowptr[NN + 1];
__device__ int   g_fill[NN];
__device__ int   g_csrsrc[NT];

// ---------------- CSR build ----------------
__global__ void k_deg_init() {
    int i = blockIdx.x * blockDim.x + threadIdx.x;
    if (i < NN) g_deg[i] = 1;   // self loop
}

__global__ void k_count(const int* __restrict__ edge) {
    int e = blockIdx.x * blockDim.x + threadIdx.x;
    if (e < NE) atomicAdd(&g_deg[edge[NE + e]], 1);
}

__global__ __launch_bounds__(1024) void k_scan() {
    __shared__ int sw[33];
    __shared__ int s_base;
    if (threadIdx.x == 0) s_base = 0;
    __syncthreads();
    const int lane = threadIdx.x & 31, warp = threadIdx.x >> 5;
    for (int base = 0; base < NN; base += 4096) {
        int idx = base + threadIdx.x * 4;
        int v0 = 0, v1 = 0, v2 = 0, v3 = 0;
        if (idx + 3 < NN) {
            int4 v = *(const int4*)&g_deg[idx];
            v0 = v.x; v1 = v.y; v2 = v.z; v3 = v.w;
        } else {
            if (idx     < NN) v0 = g_deg[idx];
            if (idx + 1 < NN) v1 = g_deg[idx + 1];
            if (idx + 2 < NN) v2 = g_deg[idx + 2];
            if (idx + 3 < NN) v3 = g_deg[idx + 3];
        }
        int s0 = v0, s1 = s0 + v1, s2 = s1 + v2, s3 = s2 + v3;
        int incl = s3;
        #pragma unroll
        for (int o = 1; o < 32; o <<= 1) {
            int t = __shfl_up_sync(0xffffffffu, incl, o);
            if (lane >= o) incl += t;
        }
        if (lane == 31) sw[warp + 1] = incl;
        __syncthreads();
        if (threadIdx.x == 0) {
            sw[0] = 0;
            int acc = 0;
            #pragma unroll
            for (int w = 1; w <= 32; w++) { acc += sw[w]; sw[w] = acc; }
        }
        __syncthreads();
        int tbase = s_base + sw[warp] + (incl - s3);
        if (idx     < NN) { g_rowptr[idx]     = tbase;      g_fill[idx]     = tbase; }
        if (idx + 1 < NN) { g_rowptr[idx + 1] = tbase + s0; g_fill[idx + 1] = tbase + s0; }
        if (idx + 2 < NN) { g_rowptr[idx + 2] = tbase + s1; g_fill[idx + 2] = tbase + s1; }
        if (idx + 3 < NN) { g_rowptr[idx + 3] = tbase + s2; g_fill[idx + 3] = tbase + s2; }
        __syncthreads();
        if (threadIdx.x == 0) s_base += sw[32];
        __syncthreads();
    }
    if (threadIdx.x == 0) g_rowptr[NN] = s_base;
}

__global__ void k_scatter(const int* __restrict__ edge) {
    int t = blockIdx.x * blockDim.x + threadIdx.x;
    if (t < NE) {
        int d = edge[NE + t];
        int s = edge[t];
        int pos = atomicAdd(&g_fill[d], 1);
        g_csrsrc[pos] = s;
    } else if (t < NT) {
        int i = t - NE;
        int pos = atomicAdd(&g_fill[i], 1);
        g_csrsrc[pos] = i;
    }
}

// ------- double-buffered SGEMM, As transposed [BK][BM+4], float4 frags -------
template <int BM, int BN, int BK, int TM, int TN>
__device__ __forceinline__
void sgemm_body(const float* __restrict__ A, const float* __restrict__ B,
                float* __restrict__ C, int M, int K, int N) {
    constexpr int THREADS = 256;
    constexpr int NA = BM * BK / 4 / THREADS;   // float4 per thread (A tile)
    constexpr int NB = BK * BN / 4 / THREADS;   // float4 per thread (B tile)
    __shared__ float As[2][BK][BM + 4];
    __shared__ float Bs[2][BK][BN];
    const int tx = threadIdx.x;
    const int tcol = tx % (BN / TN);
    const int trow = tx / (BN / TN);
    const int rowBase = blockIdx.x * BM;
    const int colBase = blockIdx.y * BN;

    float4 aReg[NA], bReg[NB];

    float acc[TM][TN];
    #pragma unroll
    for (int i = 0; i < TM; i++)
        #pragma unroll
        for (int j = 0; j < TN; j++) acc[i][j] = 0.f;

    // --- prologue: tile 0 ---
    #pragma unroll
    for (int i = 0; i < NA; i++) {
        int id = tx + i * THREADS;
        int r = id / (BK / 4), c4 = id % (BK / 4);
        int gr = rowBase + r;
        aReg[i] = (gr < M) ? *(const float4*)&A[(long long)gr * K + c4 * 4]
                           : make_float4(0.f, 0.f, 0.f, 0.f);
    }
    #pragma unroll
    for (int i = 0; i < NB; i++) {
        int id = tx + i * THREADS;
        int r = id / (BN / 4), c4 = id % (BN / 4);
        bReg[i] = *(const float4*)&B[r * N + colBase + c4 * 4];
    }
    #pragma unroll
    for (int i = 0; i < NA; i++) {
        int id = tx + i * THREADS;
        int r = id / (BK / 4), c4 = id % (BK / 4);
        As[0][c4 * 4 + 0][r] = aReg[i].x;
        As[0][c4 * 4 + 1][r] = aReg[i].y;
        As[0][c4 * 4 + 2][r] = aReg[i].z;
        As[0][c4 * 4 + 3][r] = aReg[i].w;
    }
    #pragma unroll
    for (int i = 0; i < NB; i++) {
        int id = tx + i * THREADS;
        int r = id / (BN / 4), c4 = id % (BN / 4);
        *(float4*)&Bs[0][r][c4 * 4] = bReg[i];
    }
    __syncthreads();

    const int nt = K / BK;
    for (int t = 0; t < nt; t++) {
        const int buf = t & 1;
        if (t + 1 < nt) {
            const int k0 = (t + 1) * BK;
            #pragma unroll
            for (int i = 0; i < NA; i++) {
                int id = tx + i * THREADS;
                int r = id / (BK / 4), c4 = id % (BK / 4);
                int gr = rowBase + r;
                aReg[i] = (gr < M) ? *(const float4*)&A[(long long)gr * K + k0 + c4 * 4]
                                   : make_float4(0.f, 0.f, 0.f, 0.f);
            }
            #pragma unroll
            for (int i = 0; i < NB; i++) {
                int id = tx + i * THREADS;
                int r = id / (BN / 4), c4 = id % (BN / 4);
                bReg[i] = *(const float4*)&B[(k0 + r) * N + colBase + c4 * 4];
            }
        }
        #pragma unroll
        for (int k = 0; k < BK; k++) {
            float a[TM], b[TN];
            #pragma unroll
            for (int i = 0; i < TM; i += 4)
                *(float4*)&a[i] = *(const float4*)&As[buf][k][trow * TM + i];
            #pragma unroll
            for (int j = 0; j < TN; j += 4)
                *(float4*)&b[j] = *(const float4*)&Bs[buf][k][tcol * TN + j];
            #pragma unroll
            for (int i = 0; i < TM; i++)
                #pragma unroll
                for (int j = 0; j < TN; j++)
                    acc[i][j] = fmaf(a[i], b[j], acc[i][j]);
        }
        if (t + 1 < nt) {
            __syncthreads();
            #pragma unroll
            for (int i = 0; i < NA; i++) {
                int id = tx + i * THREADS;
                int r = id / (BK / 4), c4 = id % (BK / 4);
                As[buf ^ 1][c4 * 4 + 0][r] = aReg[i].x;
                As[buf ^ 1][c4 * 4 + 1][r] = aReg[i].y;
                As[buf ^ 1][c4 * 4 + 2][r] = aReg[i].z;
                As[buf ^ 1][c4 * 4 + 3][r] = aReg[i].w;
            }
            #pragma unroll
            for (int i = 0; i < NB; i++) {
                int id = tx + i * THREADS;
                int r = id / (BN / 4), c4 = id % (BN / 4);
                *(float4*)&Bs[buf ^ 1][r][c4 * 4] = bReg[i];
            }
            __syncthreads();
        }
    }
    #pragma unroll
    for (int i = 0; i < TM; i++) {
        int gr = rowBase + trow * TM + i;
        if (gr < M) {
            #pragma unroll
            for (int j = 0; j < TN; j += 4)
                *(float4*)&C[(long long)gr * N + colBase + tcol * TN + j] =
                    *(float4*)&acc[i][j];
        }
    }
}

__global__ __launch_bounds__(256)
void sgemm1_kernel(const float* __restrict__ A, const float* __restrict__ B) {
    sgemm_body<128, 128, 16, 8, 8>(A, B, g_h1, NN, FIN, F1);
}

__global__ __launch_bounds__(256)
void sgemm2_kernel(const float* __restrict__ B) {
    sgemm_body<128, 64, 16, 8, 4>(g_out1, B, g_h2, NN, F1, F2);
}

// ---------------- alpha projections ----------------
__global__ void alpha1_kernel(const float* __restrict__ a_src,
                              const float* __restrict__ a_dst) {
    int warp = threadIdx.x >> 5, lane = threadIdx.x & 31;
    int node = blockIdx.x * 2 + (warp >> 2);
    int h = warp & 3;
    if (node >= NN) return;
    const float* row = g_h1 + (long long)node * F1 + h * 64;
    float v0 = row[lane], v1 = row[lane + 32];
    float s = v0 * a_src[h * 64 + lane] + v1 * a_src[h * 64 + lane + 32];
    float d = v0 * a_dst[h * 64 + lane] + v1 * a_dst[h * 64 + lane + 32];
    #pragma unroll
    for (int o = 16; o > 0; o >>= 1) {
        s += __shfl_down_sync(0xffffffffu, s, o);
        d += __shfl_down_sync(0xffffffffu, d, o);
    }
    if (lane == 0) { g_as1[node * 4 + h] = s; g_ad1[node * 4 + h] = d; }
}

__global__ void alpha2_kernel(const float* __restrict__ a_src,
                              const float* __restrict__ a_dst) {
    int warp = threadIdx.x >> 5, lane = threadIdx.x & 31;
    int node = blockIdx.x * 8 + warp;
    if (node >= NN) return;
    float v0 = g_h2[(long long)node * F2 + lane];
    float v1 = g_h2[(long long)node * F2 + lane + 32];
    float s = v0 * a_src[lane] + v1 * a_src[lane + 32];
    float d = v0 * a_dst[lane] + v1 * a_dst[lane + 32];
    #pragma unroll
    for (int o = 16; o > 0; o >>= 1) {
        s += __shfl_down_sync(0xffffffffu, s, o);
        d += __shfl_down_sync(0xffffffffu, d, o);
    }
    if (lane == 0) { g_as2[node] = s; g_ad2[node] = d; }
}

__device__ __forceinline__ float lrelu(float x) {
    return x > 0.f ? x : NEG_SLOPE * x;
}

// ---------------- layer 1 aggregation: 64 threads per dst, float4 channels ----
__global__ __launch_bounds__(64)
void agg1_kernel(const float* __restrict__ b1) {
    int d = blockIdx.x;
    int t = threadIdx.x;
    int h = t >> 4;
    int beg = g_rowptr[d], end = g_rowptr[d + 1];
    float adv = g_ad1[d * 4 + h];

    float m = -1e30f;
    for (int i = beg + (t & 15); i < end; i += 16) {
        int s = g_csrsrc[i];
        m = fmaxf(m, lrelu(g_as1[s * 4 + h] + adv));
    }
    #pragma unroll
    for (int o = 8; o > 0; o >>= 1)
        m = fmaxf(m, __shfl_xor_sync(0xffffffffu, m, o, 16));

    const float4* __restrict__ h1v = (const float4*)g_h1;
    float ax = 0.f, ay = 0.f, az = 0.f, aw = 0.f, den = 0.f;
    int i = beg;
    for (; i + 1 < end; i += 2) {
        int s0 = g_csrsrc[i], s1 = g_csrsrc[i + 1];
        float4 v0 = h1v[(long long)s0 * 64 + t];
        float4 v1 = h1v[(long long)s1 * 64 + t];
        float p0 = __expf(lrelu(g_as1[s0 * 4 + h] + adv) - m);
        float p1 = __expf(lrelu(g_as1[s1 * 4 + h] + adv) - m);
        den += p0 + p1;
        ax = fmaf(p0, v0.x, ax); ax = fmaf(p1, v1.x, ax);
        ay = fmaf(p0, v0.y, ay); ay = fmaf(p1, v1.y, ay);
        az = fmaf(p0, v0.z, az); az = fmaf(p1, v1.z, az);
        aw = fmaf(p0, v0.w, aw); aw = fmaf(p1, v1.w, aw);
    }
    if (i < end) {
        int s0 = g_csrsrc[i];
        float4 v0 = h1v[(long long)s0 * 64 + t];
        float p0 = __expf(lrelu(g_as1[s0 * 4 + h] + adv) - m);
        den += p0;
        ax = fmaf(p0, v0.x, ax); ay = fmaf(p0, v0.y, ay);
        az = fmaf(p0, v0.z, az); aw = fmaf(p0, v0.w, aw);
    }
    float inv = 1.f / (den + 1e-16f);
    float4 bv = ((const float4*)b1)[t];
    float4 o;
    o.x = fmaxf(ax * inv + bv.x, 0.f);
    o.y = fmaxf(ay * inv + bv.y, 0.f);
    o.z = fmaxf(az * inv + bv.z, 0.f);
    o.w = fmaxf(aw * inv + bv.w, 0.f);
    ((float4*)g_out1)[(long long)d * 64 + t] = o;
}

// ---------------- layer 2 aggregation: 4 dsts per 64-thread block ------------
__global__ __launch_bounds__(64)
void agg2_kernel(const float* __restrict__ b2, float* __restrict__ out) {
    int t = threadIdx.x;
    int g = t >> 4;
    int l = t & 15;
    int d = blockIdx.x * 4 + g;
    if (d >= NN) return;
    int beg = g_rowptr[d], end = g_rowptr[d + 1];
    float adv = g_ad2[d];

    float m = -1e30f;
    for (int i = beg + l; i < end; i += 16) {
        int s = g_csrsrc[i];
        m = fmaxf(m, lrelu(g_as2[s] + adv));
    }
    #pragma unroll
    for (int o = 8; o > 0; o >>= 1)
        m = fmaxf(m, __shfl_xor_sync(0xffffffffu, m, o, 16));

    const float4* __restrict__ h2v = (const float4*)g_h2;
    float ax = 0.f, ay = 0.f, az = 0.f, aw = 0.f, den = 0.f;
    int i = beg;
    for (; i + 1 < end; i += 2) {
        int s0 = g_csrsrc[i], s1 = g_csrsrc[i + 1];
        float4 v0 = h2v[(long long)s0 * 16 + l];
        float4 v1 = h2v[(long long)s1 * 16 + l];
        float p0 = __expf(lrelu(g_as2[s0] + adv) - m);
        float p1 = __expf(lrelu(g_as2[s1] + adv) - m);
        den += p0 + p1;
        ax = fmaf(p0, v0.x, ax); ax = fmaf(p1, v1.x, ax);
        ay = fmaf(p0, v0.y, ay); ay = fmaf(p1, v1.y, ay);
        az = fmaf(p0, v0.z, az); az = fmaf(p1, v1.z, az);
        aw = fmaf(p0, v0.w, aw); aw = fmaf(p1, v1.w, aw);
    }
    if (i < end) {
        int s0 = g_csrsrc[i];
        float4 v0 = h2v[(long long)s0 * 16 + l];
        float p0 = __expf(lrelu(g_as2[s0] + adv) - m);
        den += p0;
        ax = fmaf(p0, v0.x, ax); ay = fmaf(p0, v0.y, ay);
        az = fmaf(p0, v0.z, az); aw = fmaf(p0, v0.w, aw);
    }
    float inv = 1.f / (den + 1e-16f);
    float4 bv = ((const float4*)b2)[l];
    float4 o;
    o.x = ax * inv + bv.x;
    o.y = ay * inv + bv.y;
    o.z = az * inv + bv.z;
    o.w = aw * inv + bv.w;
    ((float4*)out)[(long long)d * 16 + l] = o;
}

// ---------------- launch ----------------
extern "C" void kernel_launch(void* const* d_in, const int* in_sizes, int n_in,
                              void* d_out, int out_size) {
    const float* x      = (const float*)d_in[0];
    const int*   edge   = (const int*)d_in[1];   // int32 (JAX x64 disabled)
    const float* W1     = (const float*)d_in[2];
    const float* a_src1 = (const float*)d_in[3];
    const float* a_dst1 = (const float*)d_in[4];
    const float* b1     = (const float*)d_in[5];
    const float* W2     = (const float*)d_in[6];
    const float* a_src2 = (const float*)d_in[7];
    const float* a_dst2 = (const float*)d_in[8];
    const float* b2     = (const float*)d_in[9];
    float* out = (float*)d_out;

    k_deg_init<<<(NN + 255) / 256, 256>>>();
    k_count<<<(NE + 255) / 256, 256>>>(edge);
    k_scan<<<1, 1024>>>();

    // idx 3: GEMM1 (profiled slot)
    {
        dim3 grid((NN + 127) / 128, F1 / 128);
        sgemm1_kernel<<<grid, 256>>>(x, W1);
    }

    k_scatter<<<(NT + 255) / 256, 256>>>(edge);
    alpha1_kernel<<<(NN + 1) / 2, 256>>>(a_src1, a_dst1);
    agg1_kernel<<<NN, 64>>>(b1);

    {
        dim3 grid((NN + 127) / 128, 1);
        sgemm2_kernel<<<grid, 256>>>(W2);
    }
    alpha2_kernel<<<(NN + 7) / 8, 256>>>(a_src2, a_dst2);
    agg2_kernel<<<(NN + 3) / 4, 64>>>(b2, out);
}

// round 6
// speedup vs baseline: 1.8988x; 1.0114x over previous
#include <cuda_runtime.h>
#include <cuda_bf16.h>
#include <math.h>

#define NN 50000
#define NE 800000
#define NT (NE + NN)
#define FIN 128
#define F1 256
#define H1HEADS 4
#define F2 64
#define NEG_SLOPE 0.2f

// -------- scratch (device globals) --------
__device__ float g_h1[NN * F1];
__device__ float g_out1[NN * F1];
__device__ float g_h2[NN * F2];
__device__ float g_as1[NN * H1HEADS];
__device__ float g_ad1[NN * H1HEADS];
__device__ float g_as2[NN];
__device__ float g_ad2[NN];
__device__ int   g_deg[NN];
__device__ int   g_rowptr[NN + 1];
__device__ int   g_fill[NN];
__device__ int   g_csrsrc[NT];

// ---------------- packed fp32x2 helpers (sm_100+) ----------------
__device__ __forceinline__ unsigned long long pack2(float x) {
    unsigned long long r;
    asm("mov.b64 %0, {%1, %1};" : "=l"(r) : "f"(x));
    return r;
}
__device__ __forceinline__ void fma2(unsigned long long& d,
                                     unsigned long long a,
                                     unsigned long long b) {
    asm("fma.rn.f32x2 %0, %1, %2, %0;" : "+l"(d) : "l"(a), "l"(b));
}

// ---------------- CSR build ----------------
__global__ void k_deg_init() {
    int i = blockIdx.x * blockDim.x + threadIdx.x;
    if (i < NN) g_deg[i] = 1;   // self loop
}

__global__ void k_count(const int* __restrict__ edge) {
    int e = blockIdx.x * blockDim.x + threadIdx.x;
    if (e < NE) atomicAdd(&g_deg[edge[NE + e]], 1);
}

__global__ __launch_bounds__(1024) void k_scan() {
    __shared__ int sw[33];
    __shared__ int s_base;
    if (threadIdx.x == 0) s_base = 0;
    __syncthreads();
    const int lane = threadIdx.x & 31, warp = threadIdx.x >> 5;
    for (int base = 0; base < NN; base += 4096) {
        int idx = base + threadIdx.x * 4;
        int v0 = 0, v1 = 0, v2 = 0, v3 = 0;
        if (idx + 3 < NN) {
            int4 v = *(const int4*)&g_deg[idx];
            v0 = v.x; v1 = v.y; v2 = v.z; v3 = v.w;
        } else {
            if (idx     < NN) v0 = g_deg[idx];
            if (idx + 1 < NN) v1 = g_deg[idx + 1];
            if (idx + 2 < NN) v2 = g_deg[idx + 2];
            if (idx + 3 < NN) v3 = g_deg[idx + 3];
        }
        int s0 = v0, s1 = s0 + v1, s2 = s1 + v2, s3 = s2 + v3;
        int incl = s3;
        #pragma unroll
        for (int o = 1; o < 32; o <<= 1) {
            int t = __shfl_up_sync(0xffffffffu, incl, o);
            if (lane >= o) incl += t;
        }
        if (lane == 31) sw[warp + 1] = incl;
        __syncthreads();
        if (threadIdx.x == 0) {
            sw[0] = 0;
            int acc = 0;
            #pragma unroll
            for (int w = 1; w <= 32; w++) { acc += sw[w]; sw[w] = acc; }
        }
        __syncthreads();
        int tbase = s_base + sw[warp] + (incl - s3);
        if (idx     < NN) { g_rowptr[idx]     = tbase;      g_fill[idx]     = tbase; }
        if (idx + 1 < NN) { g_rowptr[idx + 1] = tbase + s0; g_fill[idx + 1] = tbase + s0; }
        if (idx + 2 < NN) { g_rowptr[idx + 2] = tbase + s1; g_fill[idx + 2] = tbase + s1; }
        if (idx + 3 < NN) { g_rowptr[idx + 3] = tbase + s2; g_fill[idx + 3] = tbase + s2; }
        __syncthreads();
        if (threadIdx.x == 0) s_base += sw[32];
        __syncthreads();
    }
    if (threadIdx.x == 0) g_rowptr[NN] = s_base;
}

__global__ void k_scatter(const int* __restrict__ edge) {
    int t = blockIdx.x * blockDim.x + threadIdx.x;
    if (t < NE) {
        int d = edge[NE + t];
        int s = edge[t];
        int pos = atomicAdd(&g_fill[d], 1);
        g_csrsrc[pos] = s;
    } else if (t < NT) {
        int i = t - NE;
        int pos = atomicAdd(&g_fill[i], 1);
        g_csrsrc[pos] = i;
    }
}

// --- double-buffered SGEMM, packed f32x2 mainloop (pairs along N) ---
template <int BM, int BN, int BK, int TM, int TN>
__device__ __forceinline__
void sgemm_body(const float* __restrict__ A, const float* __restrict__ B,
                float* __restrict__ C, int M, int K, int N) {
    constexpr int THREADS = 256;
    constexpr int NA = BM * BK / 4 / THREADS;
    constexpr int NB = BK * BN / 4 / THREADS;
    constexpr int TN2 = TN / 2;
    __shared__ float As[2][BK][BM + 4];
    __shared__ float Bs[2][BK][BN];
    const int tx = threadIdx.x;
    const int tcol = tx % (BN / TN);
    const int trow = tx / (BN / TN);
    const int rowBase = blockIdx.x * BM;
    const int colBase = blockIdx.y * BN;

    float4 aReg[NA], bReg[NB];

    unsigned long long acc2[TM][TN2];
    #pragma unroll
    for (int i = 0; i < TM; i++)
        #pragma unroll
        for (int j = 0; j < TN2; j++) acc2[i][j] = 0ull;

    // --- prologue: tile 0 ---
    #pragma unroll
    for (int i = 0; i < NA; i++) {
        int id = tx + i * THREADS;
        int r = id / (BK / 4), c4 = id % (BK / 4);
        int gr = rowBase + r;
        aReg[i] = (gr < M) ? *(const float4*)&A[(long long)gr * K + c4 * 4]
                           : make_float4(0.f, 0.f, 0.f, 0.f);
    }
    #pragma unroll
    for (int i = 0; i < NB; i++) {
        int id = tx + i * THREADS;
        int r = id / (BN / 4), c4 = id % (BN / 4);
        bReg[i] = *(const float4*)&B[r * N + colBase + c4 * 4];
    }
    #pragma unroll
    for (int i = 0; i < NA; i++) {
        int id = tx + i * THREADS;
        int r = id / (BK / 4), c4 = id % (BK / 4);
        As[0][c4 * 4 + 0][r] = aReg[i].x;
        As[0][c4 * 4 + 1][r] = aReg[i].y;
        As[0][c4 * 4 + 2][r] = aReg[i].z;
        As[0][c4 * 4 + 3][r] = aReg[i].w;
    }
    #pragma unroll
    for (int i = 0; i < NB; i++) {
        int id = tx + i * THREADS;
        int r = id / (BN / 4), c4 = id % (BN / 4);
        *(float4*)&Bs[0][r][c4 * 4] = bReg[i];
    }
    __syncthreads();

    const int nt = K / BK;
    for (int t = 0; t < nt; t++) {
        const int buf = t & 1;
        if (t + 1 < nt) {
            const int k0 = (t + 1) * BK;
            #pragma unroll
            for (int i = 0; i < NA; i++) {
                int id = tx + i * THREADS;
                int r = id / (BK / 4), c4 = id % (BK / 4);
                int gr = rowBase + r;
                aReg[i] = (gr < M) ? *(const float4*)&A[(long long)gr * K + k0 + c4 * 4]
                                   : make_float4(0.f, 0.f, 0.f, 0.f);
            }
            #pragma unroll
            for (int i = 0; i < NB; i++) {
                int id = tx + i * THREADS;
                int r = id / (BN / 4), c4 = id % (BN / 4);
                bReg[i] = *(const float4*)&B[(k0 + r) * N + colBase + c4 * 4];
            }
        }
        #pragma unroll
        for (int k = 0; k < BK; k++) {
            float a[TM];
            unsigned long long a2[TM], b2[TN2];
            #pragma unroll
            for (int i = 0; i < TM; i += 4)
                *(float4*)&a[i] = *(const float4*)&As[buf][k][trow * TM + i];
            #pragma unroll
            for (int i = 0; i < TM; i++) a2[i] = pack2(a[i]);
            #pragma unroll
            for (int j = 0; j < TN2; j += 2) {
                ulonglong2 bb = *(const ulonglong2*)&Bs[buf][k][tcol * TN + j * 2];
                b2[j] = bb.x; b2[j + 1] = bb.y;
            }
            #pragma unroll
            for (int i = 0; i < TM; i++)
                #pragma unroll
                for (int j = 0; j < TN2; j++)
                    fma2(acc2[i][j], a2[i], b2[j]);
        }
        if (t + 1 < nt) {
            __syncthreads();
            #pragma unroll
            for (int i = 0; i < NA; i++) {
                int id = tx + i * THREADS;
                int r = id / (BK / 4), c4 = id % (BK / 4);
                As[buf ^ 1][c4 * 4 + 0][r] = aReg[i].x;
                As[buf ^ 1][c4 * 4 + 1][r] = aReg[i].y;
                As[buf ^ 1][c4 * 4 + 2][r] = aReg[i].z;
                As[buf ^ 1][c4 * 4 + 3][r] = aReg[i].w;
            }
            #pragma unroll
            for (int i = 0; i < NB; i++) {
                int id = tx + i * THREADS;
                int r = id / (BN / 4), c4 = id % (BN / 4);
                *(float4*)&Bs[buf ^ 1][r][c4 * 4] = bReg[i];
            }
            __syncthreads();
        }
    }
    #pragma unroll
    for (int i = 0; i < TM; i++) {
        int gr = rowBase + trow * TM + i;
        if (gr < M) {
            #pragma unroll
            for (int j = 0; j < TN2; j += 2) {
                ulonglong2 st;
                st.x = acc2[i][j];
                st.y = acc2[i][j + 1];
                *(ulonglong2*)&C[(long long)gr * N + colBase + tcol * TN + j * 2] = st;
            }
        }
    }
}

__global__ __launch_bounds__(256, 2)
void sgemm1_kernel(const float* __restrict__ A, const float* __restrict__ B) {
    sgemm_body<128, 128, 16, 8, 8>(A, B, g_h1, NN, FIN, F1);
}

__global__ __launch_bounds__(256, 2)
void sgemm2_kernel(const float* __restrict__ B) {
    sgemm_body<128, 64, 16, 8, 4>(g_out1, B, g_h2, NN, F1, F2);
}

// ---------------- alpha projections ----------------
__global__ void alpha1_kernel(const float* __restrict__ a_src,
                              const float* __restrict__ a_dst) {
    int warp = threadIdx.x >> 5, lane = threadIdx.x & 31;
    int node = blockIdx.x * 2 + (warp >> 2);
    int h = warp & 3;
    if (node >= NN) return;
    const float* row = g_h1 + (long long)node * F1 + h * 64;
    float v0 = row[lane], v1 = row[lane + 32];
    float s = v0 * a_src[h * 64 + lane] + v1 * a_src[h * 64 + lane + 32];
    float d = v0 * a_dst[h * 64 + lane] + v1 * a_dst[h * 64 + lane + 32];
    #pragma unroll
    for (int o = 16; o > 0; o >>= 1) {
        s += __shfl_down_sync(0xffffffffu, s, o);
        d += __shfl_down_sync(0xffffffffu, d, o);
    }
    if (lane == 0) { g_as1[node * 4 + h] = s; g_ad1[node * 4 + h] = d; }
}

__global__ void alpha2_kernel(const float* __restrict__ a_src,
                              const float* __restrict__ a_dst) {
    int warp = threadIdx.x >> 5, lane = threadIdx.x & 31;
    int node = blockIdx.x * 8 + warp;
    if (node >= NN) return;
    float v0 = g_h2[(long long)node * F2 + lane];
    float v1 = g_h2[(long long)node * F2 + lane + 32];
    float s = v0 * a_src[lane] + v1 * a_src[lane + 32];
    float d = v0 * a_dst[lane] + v1 * a_dst[lane + 32];
    #pragma unroll
    for (int o = 16; o > 0; o >>= 1) {
        s += __shfl_down_sync(0xffffffffu, s, o);
        d += __shfl_down_sync(0xffffffffu, d, o);
    }
    if (lane == 0) { g_as2[node] = s; g_ad2[node] = d; }
}

__device__ __forceinline__ float lrelu(float x) {
    return x > 0.f ? x : NEG_SLOPE * x;
}

// ---------------- layer 1 aggregation: 64 threads per dst, float4 channels ----
__global__ __launch_bounds__(64)
void agg1_kernel(const float* __restrict__ b1) {
    int d = blockIdx.x;
    int t = threadIdx.x;
    int h = t >> 4;
    int beg = g_rowptr[d], end = g_rowptr[d + 1];
    float adv = g_ad1[d * 4 + h];

    float m = -1e30f;
    for (int i = beg + (t & 15); i < end; i += 16) {
        int s = g_csrsrc[i];
        m = fmaxf(m, lrelu(g_as1[s * 4 + h] + adv));
    }
    #pragma unroll
    for (int o = 8; o > 0; o >>= 1)
        m = fmaxf(m, __shfl_xor_sync(0xffffffffu, m, o, 16));

    const float4* __restrict__ h1v = (const float4*)g_h1;
    float ax = 0.f, ay = 0.f, az = 0.f, aw = 0.f, den = 0.f;
    int i = beg;
    for (; i + 1 < end; i += 2) {
        int s0 = g_csrsrc[i], s1 = g_csrsrc[i + 1];
        float4 v0 = h1v[(long long)s0 * 64 + t];
        float4 v1 = h1v[(long long)s1 * 64 + t];
        float p0 = __expf(lrelu(g_as1[s0 * 4 + h] + adv) - m);
        float p1 = __expf(lrelu(g_as1[s1 * 4 + h] + adv) - m);
        den += p0 + p1;
        ax = fmaf(p0, v0.x, ax); ax = fmaf(p1, v1.x, ax);
        ay = fmaf(p0, v0.y, ay); ay = fmaf(p1, v1.y, ay);
        az = fmaf(p0, v0.z, az); az = fmaf(p1, v1.z, az);
        aw = fmaf(p0, v0.w, aw); aw = fmaf(p1, v1.w, aw);
    }
    if (i < end) {
        int s0 = g_csrsrc[i];
        float4 v0 = h1v[(long long)s0 * 64 + t];
        float p0 = __expf(lrelu(g_as1[s0 * 4 + h] + adv) - m);
        den += p0;
        ax = fmaf(p0, v0.x, ax); ay = fmaf(p0, v0.y, ay);
        az = fmaf(p0, v0.z, az); aw = fmaf(p0, v0.w, aw);
    }
    float inv = 1.f / (den + 1e-16f);
    float4 bv = ((const float4*)b1)[t];
    float4 o;
    o.x = fmaxf(ax * inv + bv.x, 0.f);
    o.y = fmaxf(ay * inv + bv.y, 0.f);
    o.z = fmaxf(az * inv + bv.z, 0.f);
    o.w = fmaxf(aw * inv + bv.w, 0.f);
    ((float4*)g_out1)[(long long)d * 64 + t] = o;
}

// ---------------- layer 2 aggregation: 4 dsts per 64-thread block ------------
__global__ __launch_bounds__(64)
void agg2_kernel(const float* __restrict__ b2, float* __restrict__ out) {
    int t = threadIdx.x;
    int g = t >> 4;
    int l = t & 15;
    int d = blockIdx.x * 4 + g;
    if (d >= NN) return;
    int beg = g_rowptr[d], end = g_rowptr[d + 1];
    float adv = g_ad2[d];

    float m = -1e30f;
    for (int i = beg + l; i < end; i += 16) {
        int s = g_csrsrc[i];
        m = fmaxf(m, lrelu(g_as2[s] + adv));
    }
    #pragma unroll
    for (int o = 8; o > 0; o >>= 1)
        m = fmaxf(m, __shfl_xor_sync(0xffffffffu, m, o, 16));

    const float4* __restrict__ h2v = (const float4*)g_h2;
    float ax = 0.f, ay = 0.f, az = 0.f, aw = 0.f, den = 0.f;
    int i = beg;
    for (; i + 1 < end; i += 2) {
        int s0 = g_csrsrc[i], s1 = g_csrsrc[i + 1];
        float4 v0 = h2v[(long long)s0 * 16 + l];
        float4 v1 = h2v[(long long)s1 * 16 + l];
        float p0 = __expf(lrelu(g_as2[s0] + adv) - m);
        float p1 = __expf(lrelu(g_as2[s1] + adv) - m);
        den += p0 + p1;
        ax = fmaf(p0, v0.x, ax); ax = fmaf(p1, v1.x, ax);
        ay = fmaf(p0, v0.y, ay); ay = fmaf(p1, v1.y, ay);
        az = fmaf(p0, v0.z, az); az = fmaf(p1, v1.z, az);
        aw = fmaf(p0, v0.w, aw); aw = fmaf(p1, v1.w, aw);
    }
    if (i < end) {
        int s0 = g_csrsrc[i];
        float4 v0 = h2v[(long long)s0 * 16 + l];
        float p0 = __expf(lrelu(g_as2[s0] + adv) - m);
        den += p0;
        ax = fmaf(p0, v0.x, ax); ay = fmaf(p0, v0.y, ay);
        az = fmaf(p0, v0.z, az); aw = fmaf(p0, v0.w, aw);
    }
    float inv = 1.f / (den + 1e-16f);
    float4 bv = ((const float4*)b2)[l];
    float4 o;
    o.x = ax * inv + bv.x;
    o.y = ay * inv + bv.y;
    o.z = az * inv + bv.z;
    o.w = aw * inv + bv.w;
    ((float4*)out)[(long long)d * 16 + l] = o;
}

// ---------------- launch ----------------
extern "C" void kernel_launch(void* const* d_in, const int* in_sizes, int n_in,
                              void* d_out, int out_size) {
    const float* x      = (const float*)d_in[0];
    const int*   edge   = (const int*)d_in[1];   // int32 (JAX x64 disabled)
    const float* W1     = (const float*)d_in[2];
    const float* a_src1 = (const float*)d_in[3];
    const float* a_dst1 = (const float*)d_in[4];
    const float* b1     = (const float*)d_in[5];
    const float* W2     = (const float*)d_in[6];
    const float* a_src2 = (const float*)d_in[7];
    const float* a_dst2 = (const float*)d_in[8];
    const float* b2     = (const float*)d_in[9];
    float* out = (float*)d_out;

    k_deg_init<<<(NN + 255) / 256, 256>>>();
    k_count<<<(NE + 255) / 256, 256>>>(edge);
    k_scan<<<1, 1024>>>();

    // idx 3: GEMM1 (profiled slot — verify f32x2 effect)
    {
        dim3 grid((NN + 127) / 128, F1 / 128);
        sgemm1_kernel<<<grid, 256>>>(x, W1);
    }

    k_scatter<<<(NT + 255) / 256, 256>>>(edge);
    alpha1_kernel<<<(NN + 1) / 2, 256>>>(a_src1, a_dst1);
    agg1_kernel<<<NN, 64>>>(b1);

    {
        dim3 grid((NN + 127) / 128, 1);
        sgemm2_kernel<<<grid, 256>>>(W2);
    }
    alpha2_kernel<<<(NN + 7) / 8, 256>>>(a_src2, a_dst2);
    agg2_kernel<<<(NN + 3) / 4, 64>>>(b2, out);
}